// round 1
// baseline (speedup 1.0000x reference)
#include <cuda_runtime.h>
#include <cstdint>

// ---------------------------------------------------------------------------
// LinearAttention: B=4, N=8192, D=1024, H=16, Dh=64
//   q = fm(x@wq+bq), k = fm(x@wk+bk), v = x@wv+bv      (fm = elu+1)
//   kv[b,h,d,e] = sum_n k*v ; ksum[b,h,d] = sum_n k
//   z = 1/(q . ksum + 1e-6)
//   scores = (q @ kv) * z ;  out = scores @ wo + bo
// Strategy: TF32 mma.sync (rna-rounded) for the two big GEMM stages,
//           fp32 SIMT for the small middle stages. Deterministic.
// ---------------------------------------------------------------------------

constexpr int GM = 32768;   // B*N
constexpr int GN = 1024;    // D
constexpr int GK = 1024;    // D
constexpr int BM = 128, BN = 128, BK = 32;
constexpr int AS  = 36;     // A smem row stride (floats), conflict-free frag reads
constexpr int BSS = 136;    // B smem row stride (floats)
constexpr int A_STAGE = BM * AS;    // 4608 floats
constexpr int B_STAGE = BK * BSS;   // 4352 floats
constexpr int GEMM_SMEM_BYTES = 2 * (A_STAGE + B_STAGE) * 4;  // 71680 B
constexpr int SCORES_SMEM_BYTES = (4096 + 64 + 128 * 65) * 4; // 49920 B

// Scratch (device globals: no allocation allowed in kernel_launch)
__device__ float g_Q[(size_t)GM * GN];
__device__ float g_K[(size_t)GM * GN];
__device__ float g_V[(size_t)GM * GN];
__device__ float g_S[(size_t)GM * GN];
__device__ float g_kvpart[1024 * 4160];   // [b,h,chunk][64*64 kv + 64 ksum]
__device__ float g_kv[64 * 4096];         // [b*16+h][d*64+e]
__device__ float g_ksum[64 * 64];         // [b*16+h][d]

// ---------------------------------------------------------------------------
// helpers
// ---------------------------------------------------------------------------
__device__ __forceinline__ uint32_t f2tf(float x) {
    uint32_t r;
    asm("cvt.rna.tf32.f32 %0, %1;" : "=r"(r) : "f"(x));
    return r;
}

__device__ __forceinline__ void mma_tf32(float* c, const uint32_t* a, const uint32_t* b) {
    asm volatile(
        "mma.sync.aligned.m16n8k8.row.col.f32.tf32.tf32.f32 "
        "{%0,%1,%2,%3}, {%4,%5,%6,%7}, {%8,%9}, {%0,%1,%2,%3};\n"
        : "+f"(c[0]), "+f"(c[1]), "+f"(c[2]), "+f"(c[3])
        : "r"(a[0]), "r"(a[1]), "r"(a[2]), "r"(a[3]), "r"(b[0]), "r"(b[1]));
}

__device__ __forceinline__ void cp16(void* s, const void* g) {
    uint32_t sa = (uint32_t)__cvta_generic_to_shared(s);
    asm volatile("cp.async.cg.shared.global [%0], [%1], 16;\n" :: "r"(sa), "l"(g) : "memory");
}

__device__ __forceinline__ float fm_act(float x) {
    // elu(x)+1 = x+1 (x>0) else exp(x)
    return x > 0.0f ? x + 1.0f : __expf(x);
}

// ---------------------------------------------------------------------------
// GEMM: C[M,N] = act(A[M,K] @ W[K,N] + bias)
// MODE 0: A = x (param), z in {0,1,2} selects (wq->g_Q, wk->g_K, wv->g_V), act for z<2
// MODE 1: A = g_S, W = W0 (= wo), output = Oout (d_out), no act
// ---------------------------------------------------------------------------
template <int MODE>
__global__ void __launch_bounds__(256, 2)
gemm_kernel(const float* __restrict__ Ain,
            const float* __restrict__ W0, const float* __restrict__ W1,
            const float* __restrict__ W2,
            const float* __restrict__ c0p, const float* __restrict__ c1p,
            const float* __restrict__ c2p,
            float* __restrict__ Oout)
{
    extern __shared__ float smem[];
    const int z = blockIdx.z;

    const float* A;
    const float* W;
    const float* bias;
    float* O;
    bool act;
    if (MODE == 0) {
        A    = Ain;
        W    = (z == 0) ? W0 : (z == 1 ? W1 : W2);
        bias = (z == 0) ? c0p : (z == 1 ? c1p : c2p);
        O    = (z == 0) ? g_Q : (z == 1 ? g_K : g_V);
        act  = (z < 2);
    } else {
        A = g_S; W = W0; bias = c0p; O = Oout; act = false;
    }

    const int rowBase = blockIdx.y * BM;
    const int colBase = blockIdx.x * BN;
    const int t    = threadIdx.x;
    const int lane = t & 31;
    const int wid  = t >> 5;
    const int wm   = (wid & 3) * 32;   // warp m offset within block
    const int wn   = (wid >> 2) * 64;  // warp n offset within block
    const int g    = lane >> 2;        // groupID
    const int l4   = lane & 3;         // threadID_in_group

    float* As0 = smem;                 // 2 stages of A
    float* Bs0 = smem + 2 * A_STAGE;   // 2 stages of B

    auto load_tiles = [&](int kt, int buf) {
        float* Asb = As0 + buf * A_STAGE;
        float* Bsb = Bs0 + buf * B_STAGE;
        const float* Ag = A + (size_t)rowBase * GK + kt * BK;
        const float* Wg = W + (size_t)(kt * BK) * GN + colBase;
#pragma unroll
        for (int i = 0; i < 4; i++) {
            int f  = i * 256 + t;
            int ar = f >> 3, ac = (f & 7) << 2;     // 128 rows x 8 float4
            cp16(&Asb[ar * AS + ac], &Ag[(size_t)ar * GK + ac]);
            int br = f >> 5, bc = (f & 31) << 2;    // 32 rows x 32 float4
            cp16(&Bsb[br * BSS + bc], &Wg[(size_t)br * GN + bc]);
        }
        asm volatile("cp.async.commit_group;\n" ::: "memory");
    };

    float acc[2][8][4] = {};

    load_tiles(0, 0);
    load_tiles(1, 1);

    const int NK = GK / BK;  // 32
    for (int kt = 0; kt < NK; kt++) {
        if (kt < NK - 1) { asm volatile("cp.async.wait_group 1;\n" ::: "memory"); }
        else             { asm volatile("cp.async.wait_group 0;\n" ::: "memory"); }
        __syncthreads();

        const float* Asb = As0 + (kt & 1) * A_STAGE;
        const float* Bsb = Bs0 + (kt & 1) * B_STAGE;

#pragma unroll
        for (int ks = 0; ks < 4; ks++) {
            const int k0 = ks * 8;
            uint32_t afr[2][4];
            uint32_t bfr[8][2];
#pragma unroll
            for (int mi = 0; mi < 2; mi++) {
                int r = wm + mi * 16 + g;
                afr[mi][0] = f2tf(Asb[r * AS + k0 + l4]);
                afr[mi][1] = f2tf(Asb[(r + 8) * AS + k0 + l4]);
                afr[mi][2] = f2tf(Asb[r * AS + k0 + l4 + 4]);
                afr[mi][3] = f2tf(Asb[(r + 8) * AS + k0 + l4 + 4]);
            }
#pragma unroll
            for (int ni = 0; ni < 8; ni++) {
                int n = wn + ni * 8 + g;
                bfr[ni][0] = f2tf(Bsb[(k0 + l4) * BSS + n]);
                bfr[ni][1] = f2tf(Bsb[(k0 + l4 + 4) * BSS + n]);
            }
#pragma unroll
            for (int mi = 0; mi < 2; mi++)
#pragma unroll
                for (int ni = 0; ni < 8; ni++)
                    mma_tf32(acc[mi][ni], afr[mi], bfr[ni]);
        }
        __syncthreads();
        if (kt + 2 < NK) load_tiles(kt + 2, kt & 1);
    }

    // Epilogue: bias + optional fm, float2 stores (contiguous, sector-aligned)
#pragma unroll
    for (int mi = 0; mi < 2; mi++) {
        int r = rowBase + wm + mi * 16 + g;
#pragma unroll
        for (int ni = 0; ni < 8; ni++) {
            int c = colBase + wn + ni * 8 + 2 * l4;
            float b0v = bias[c], b1v = bias[c + 1];
            float v0 = acc[mi][ni][0] + b0v;
            float v1 = acc[mi][ni][1] + b1v;
            float v2 = acc[mi][ni][2] + b0v;
            float v3 = acc[mi][ni][3] + b1v;
            if (act) { v0 = fm_act(v0); v1 = fm_act(v1); v2 = fm_act(v2); v3 = fm_act(v3); }
            float2 p0 = make_float2(v0, v1);
            float2 p1 = make_float2(v2, v3);
            *reinterpret_cast<float2*>(&O[(size_t)r * GN + c])       = p0;
            *reinterpret_cast<float2*>(&O[(size_t)(r + 8) * GN + c]) = p1;
        }
    }
}

// ---------------------------------------------------------------------------
// kv partial reduction: grid (16 chunks, 16 h, 4 b), 256 threads.
// Each block reduces 512 sequence positions into a 64x64 kv partial + ksum.
// Deterministic (no atomics).
// ---------------------------------------------------------------------------
__global__ void kv_partial_kernel()
{
    __shared__ float ks_[32 * 64];
    __shared__ float vs_[32 * 64];
    const int chunk = blockIdx.x, h = blockIdx.y, b = blockIdx.z;
    const int t  = threadIdx.x;
    const int td = (t >> 4) * 4;   // 0..60
    const int te = (t & 15) * 4;   // 0..60

    float acc[4][4] = {};
    float ksacc[4]  = {};

    const size_t base = ((size_t)b * 8192) * 1024 + (size_t)h * 64;
    const float* Kb = g_K + base;
    const float* Vb = g_V + base;

    const int nStart = chunk * 512;
    for (int n0 = nStart; n0 < nStart + 512; n0 += 32) {
        __syncthreads();
#pragma unroll
        for (int i = 0; i < 2; i++) {
            int f  = i * 256 + t;
            int nn = f >> 4, c4 = (f & 15) * 4;
            *reinterpret_cast<float4*>(&ks_[nn * 64 + c4]) =
                *reinterpret_cast<const float4*>(&Kb[(size_t)(n0 + nn) * 1024 + c4]);
            *reinterpret_cast<float4*>(&vs_[nn * 64 + c4]) =
                *reinterpret_cast<const float4*>(&Vb[(size_t)(n0 + nn) * 1024 + c4]);
        }
        __syncthreads();
#pragma unroll 4
        for (int nn = 0; nn < 32; nn++) {
            float4 kk = *reinterpret_cast<const float4*>(&ks_[nn * 64 + td]);
            float4 vv = *reinterpret_cast<const float4*>(&vs_[nn * 64 + te]);
            float kq[4] = {kk.x, kk.y, kk.z, kk.w};
            float vq[4] = {vv.x, vv.y, vv.z, vv.w};
#pragma unroll
            for (int i = 0; i < 4; i++)
#pragma unroll
                for (int j = 0; j < 4; j++)
                    acc[i][j] += kq[i] * vq[j];
            if (te == 0) {
                ksacc[0] += kk.x; ksacc[1] += kk.y; ksacc[2] += kk.z; ksacc[3] += kk.w;
            }
        }
    }

    float* P = g_kvpart + (size_t)(((b * 16 + h) * 16) + chunk) * 4160;
#pragma unroll
    for (int i = 0; i < 4; i++)
#pragma unroll
        for (int j = 0; j < 4; j++)
            P[(td + i) * 64 + te + j] = acc[i][j];
    if (te == 0) {
#pragma unroll
        for (int i = 0; i < 4; i++) P[4096 + td + i] = ksacc[i];
    }
}

// Reduce the 16 chunk-partials per (b,h). grid 64, 256 threads.
__global__ void kv_reduce_kernel()
{
    const int bh = blockIdx.x;
    const float* P = g_kvpart + (size_t)bh * 16 * 4160;
    for (int i = threadIdx.x; i < 4160; i += 256) {
        float s = 0.0f;
#pragma unroll
        for (int c = 0; c < 16; c++) s += P[c * 4160 + i];
        if (i < 4096) g_kv[bh * 4096 + i] = s;
        else          g_ksum[bh * 64 + (i - 4096)] = s;
    }
}

// ---------------------------------------------------------------------------
// scores: grid (256 row-chunks, 16 h), 128 threads, dynamic smem.
// Per row: z = 1/(q.ksum + 1e-6); scores[:,e] = z * sum_d q[d]*kv[d][e]
// ---------------------------------------------------------------------------
__global__ void scores_kernel()
{
    extern __shared__ float sm[];
    float* kv_s   = sm;               // 4096
    float* ksum_s = sm + 4096;        // 64
    float* q_s    = sm + 4160;        // 128 * 65 (stride 65: conflict-free row reads)

    const int h  = blockIdx.y;
    const int r0 = blockIdx.x * 128;
    const int b  = r0 >> 13;          // 8192 rows per batch, chunks never straddle
    const int bh = b * 16 + h;
    const int t  = threadIdx.x;

    for (int i = t; i < 4096; i += 128) kv_s[i] = g_kv[bh * 4096 + i];
    if (t < 64) ksum_s[t] = g_ksum[bh * 64 + t];

#pragma unroll
    for (int i = 0; i < 16; i++) {
        int f = i * 128 + t;
        int row = f >> 4, c4 = (f & 15) << 2;
        float4 qv = *reinterpret_cast<const float4*>(
            &g_Q[(size_t)(r0 + row) * 1024 + h * 64 + c4]);
        float* dst = &q_s[row * 65 + c4];
        dst[0] = qv.x; dst[1] = qv.y; dst[2] = qv.z; dst[3] = qv.w;
    }
    __syncthreads();

    float out_[64];
#pragma unroll
    for (int e = 0; e < 64; e++) out_[e] = 0.0f;
    float zacc = 0.0f;
    const float* qrow = &q_s[t * 65];

    for (int d = 0; d < 64; d++) {
        float q = qrow[d];
        zacc += q * ksum_s[d];
        const float4* kr = reinterpret_cast<const float4*>(&kv_s[d * 64]);
#pragma unroll
        for (int e4 = 0; e4 < 16; e4++) {
            float4 kv4 = kr[e4];  // broadcast across lanes
            out_[e4 * 4 + 0] += q * kv4.x;
            out_[e4 * 4 + 1] += q * kv4.y;
            out_[e4 * 4 + 2] += q * kv4.z;
            out_[e4 * 4 + 3] += q * kv4.w;
        }
    }

    float zv = 1.0f / (zacc + 1e-6f);
#pragma unroll
    for (int e = 0; e < 64; e++) q_s[t * 65 + e] = out_[e] * zv;  // own row only
    __syncthreads();

#pragma unroll
    for (int i = 0; i < 16; i++) {
        int f = i * 128 + t;
        int row = f >> 4, c4 = (f & 15) << 2;
        const float* src = &q_s[row * 65 + c4];
        float4 o = make_float4(src[0], src[1], src[2], src[3]);
        *reinterpret_cast<float4*>(&g_S[(size_t)(r0 + row) * 1024 + h * 64 + c4]) = o;
    }
}

// ---------------------------------------------------------------------------
// launch
// ---------------------------------------------------------------------------
extern "C" void kernel_launch(void* const* d_in, const int* in_sizes, int n_in,
                              void* d_out, int out_size)
{
    const float* x  = (const float*)d_in[0];
    const float* wq = (const float*)d_in[1];
    const float* bq = (const float*)d_in[2];
    const float* wk = (const float*)d_in[3];
    const float* bk = (const float*)d_in[4];
    const float* wv = (const float*)d_in[5];
    const float* bv = (const float*)d_in[6];
    const float* wo = (const float*)d_in[7];
    const float* bo = (const float*)d_in[8];
    float* out = (float*)d_out;
    (void)in_sizes; (void)n_in; (void)out_size;

    cudaFuncSetAttribute(gemm_kernel<0>, cudaFuncAttributeMaxDynamicSharedMemorySize,
                         GEMM_SMEM_BYTES);
    cudaFuncSetAttribute(gemm_kernel<1>, cudaFuncAttributeMaxDynamicSharedMemorySize,
                         GEMM_SMEM_BYTES);
    cudaFuncSetAttribute(scores_kernel, cudaFuncAttributeMaxDynamicSharedMemorySize,
                         SCORES_SMEM_BYTES);

    // 1) QKV projections (TF32 tensor), fm applied to q,k in epilogue
    gemm_kernel<0><<<dim3(GN / BN, GM / BM, 3), 256, GEMM_SMEM_BYTES>>>(
        x, wq, wk, wv, bq, bk, bv, nullptr);

    // 2) kv outer-product + ksum (deterministic two-pass)
    kv_partial_kernel<<<dim3(16, 16, 4), 256>>>();
    kv_reduce_kernel<<<64, 256>>>();

    // 3) scores = (q @ kv) * z
    scores_kernel<<<dim3(256, 16), 128, SCORES_SMEM_BYTES>>>();

    // 4) out = scores @ wo + bo
    gemm_kernel<1><<<dim3(GN / BN, GM / BM, 1), 256, GEMM_SMEM_BYTES>>>(
        x, wo, wo, wo, bo, bo, bo, out);
}

// round 7
// speedup vs baseline: 1.1497x; 1.1497x over previous
#include <cuda_runtime.h>
#include <cstdint>

// ---------------------------------------------------------------------------
// LinearAttention B=4 N=8192 D=1024 H=16 Dh=64
// sm_100 base-ISA build: mma.sync tf32 + ldmatrix + cp.async (NO tcgen05 —
// harness ptxas targets sm_100 without the 'a' feature set).
// ---------------------------------------------------------------------------

constexpr int GM = 32768, GN = 1024, GK = 1024;
constexpr int BM = 128, BN = 256, BK = 32;
constexpr int NKT = GK / BK;                    // 32
constexpr int STAGES = 4;                       // 4-slot ring, prefetch dist 3
constexpr int A_STAGE_B = BM * 128;             // 16384 B (128 rows x 128B)
constexpr int B_STAGE_B = BN * 128;             // 32768 B (256 n-rows x 128B)
constexpr int STAGE_B   = A_STAGE_B + B_STAGE_B; // 49152
constexpr int OFF_BIAS  = STAGES * STAGE_B;      // 196608
constexpr int GEMM_SMEM = OFF_BIAS + BN * 4;     // 197632
constexpr int SCORES_SMEM = (4096 + 64 + 256 * 65) * 4;  // 83200

// scratch (device globals; no allocation allowed)
__device__ float g_X[(size_t)GM * GN];
__device__ float g_Q[(size_t)GM * GN];
__device__ float g_K[(size_t)GM * GN];
__device__ float g_V[(size_t)GM * GN];
__device__ float g_S[(size_t)GM * GN];
__device__ float g_WT[4][(size_t)GK * GN];      // W^T (n-major), tf32-rounded
__device__ float g_kvpart[1024 * 4160];
__device__ float g_kv[64 * 4096];
__device__ float g_ksum[64 * 64];

// ---------------------------------------------------------------------------
// helpers
// ---------------------------------------------------------------------------
__device__ __forceinline__ uint32_t smem_u32(const void* p) {
    uint32_t a;
    asm("{ .reg .u64 t; cvta.to.shared.u64 t, %1; cvt.u32.u64 %0, t; }" : "=r"(a) : "l"(p));
    return a;
}
__device__ __forceinline__ uint32_t f2tf(float x) {
    uint32_t r;
    asm("cvt.rna.tf32.f32 %0, %1;" : "=r"(r) : "f"(x));
    return r;
}
__device__ __forceinline__ float rna_tf32(float x) { return __uint_as_float(f2tf(x)); }

__device__ __forceinline__ void cp16(uint32_t s, const void* g) {
    asm volatile("cp.async.cg.shared.global [%0], [%1], 16;" :: "r"(s), "l"(g) : "memory");
}
#define CP_COMMIT() asm volatile("cp.async.commit_group;" ::: "memory")

__device__ __forceinline__ float fm_act(float x) { return x > 0.0f ? x + 1.0f : __expf(x); }

__device__ __forceinline__ void ldsm4(uint32_t* d, uint32_t addr) {
    asm volatile("ldmatrix.sync.aligned.m8n8.x4.shared.b16 {%0,%1,%2,%3}, [%4];"
                 : "=r"(d[0]), "=r"(d[1]), "=r"(d[2]), "=r"(d[3]) : "r"(addr));
}
// operands are fp32 bit patterns already rounded to tf32 (HW truncation exact)
__device__ __forceinline__ void mma_tf32(float* c, const uint32_t* a, uint32_t b0, uint32_t b1) {
    asm volatile(
        "mma.sync.aligned.m16n8k8.row.col.f32.tf32.tf32.f32 "
        "{%0,%1,%2,%3}, {%4,%5,%6,%7}, {%8,%9}, {%0,%1,%2,%3};"
        : "+f"(c[0]), "+f"(c[1]), "+f"(c[2]), "+f"(c[3])
        : "r"(a[0]), "r"(a[1]), "r"(a[2]), "r"(a[3]), "r"(b0), "r"(b1));
}

#define SWZ(off) ((off) ^ (((off) >> 3) & 0x70))

// ---------------------------------------------------------------------------
// pre-passes: rna-round x; transpose + round weights to n-major WT[n][k]
// ---------------------------------------------------------------------------
__global__ void round_x_kernel(const float* __restrict__ x) {
    size_t i = ((size_t)blockIdx.x * 128 + threadIdx.x) * 4;
    float4 v = *reinterpret_cast<const float4*>(x + i);
    v.x = rna_tf32(v.x); v.y = rna_tf32(v.y); v.z = rna_tf32(v.z); v.w = rna_tf32(v.w);
    *reinterpret_cast<float4*>(g_X + i) = v;
}

__global__ void transpose_w_kernel(const float* __restrict__ w0, const float* __restrict__ w1,
                                   const float* __restrict__ w2, const float* __restrict__ w3) {
    __shared__ float tile[32][33];
    const float* W = (blockIdx.z == 0) ? w0 : (blockIdx.z == 1) ? w1 : (blockIdx.z == 2) ? w2 : w3;
    float* WT = &g_WT[blockIdx.z][0];
    int bx = blockIdx.x * 32, by = blockIdx.y * 32;   // bx: n, by: k
    int tx = threadIdx.x, ty = threadIdx.y;
#pragma unroll
    for (int i = 0; i < 32; i += 8)
        tile[ty + i][tx] = W[(size_t)(by + ty + i) * GN + bx + tx];
    __syncthreads();
#pragma unroll
    for (int i = 0; i < 32; i += 8)
        WT[(size_t)(bx + ty + i) * GK + by + tx] = rna_tf32(tile[tx][ty + i]);
}

// ---------------------------------------------------------------------------
// TF32 mma.sync GEMM, 4-stage cp.async ring, ldmatrix fragments, no in-loop cvt.
//   C[M,N] = act(A[M,K] @ W[K,N] + bias),  W given n-major (WT[n][k])
// MODE 0: A=g_X, z -> (WTq->g_Q act, WTk->g_K act, WTv->g_V)
// MODE 1: A=g_S, WTo -> Oout, no act
// 256 threads, warps 4(m) x 2(n); warp tile 32x128.
//
// Ring schedule (race-free with ONE barrier/iter): at top of iter kt, slot
// (kt+3)&3 == (kt-1)&3 holds tile kt-1, finished by all warps before this
// barrier -> safe to prefetch tile kt+3 there. Reads of kt+3 happen 3 iters
// later behind the wait_group ladder.
// ---------------------------------------------------------------------------
template <int MODE>
__global__ void __launch_bounds__(256, 1)
tc_gemm(const float* __restrict__ bias0, const float* __restrict__ bias1,
        const float* __restrict__ bias2, float* __restrict__ Oout)
{
    extern __shared__ __align__(128) char smem[];
    const uint32_t sb = smem_u32(smem);
    const int t = threadIdx.x, lane = t & 31, wid = t >> 5;
    const int z = blockIdx.z;

    const float* A;  const float* WT;  const float* bias;  float* O;  bool act;
    if (MODE == 0) {
        A = g_X; WT = &g_WT[z][0];
        bias = (z == 0) ? bias0 : (z == 1) ? bias1 : bias2;
        O = (z == 0) ? g_Q : (z == 1) ? g_K : g_V;
        act = (z < 2);
    } else {
        A = g_S; WT = &g_WT[3][0]; bias = bias0; O = Oout; act = false;
    }

    const int rowBase = blockIdx.y * BM;
    const int colBase = blockIdx.x * BN;
    const int wm = (wid & 3) * 32;      // warp m offset (4 warps over 128)
    const int wn = (wid >> 2) * 128;    // warp n offset (2 warps over 256)

    // bias -> smem
    float* bias_s = reinterpret_cast<float*>(smem + OFF_BIAS);
    if (t < BN) bias_s[t] = bias[colBase + t];

    // ---- cp.async stage loader (SW128-swizzled 128B rows) ----
    auto load_stage = [&](int kt, int s) {
        const uint32_t stg = sb + s * STAGE_B;
        const float* Ag = A + (size_t)rowBase * GK + kt * BK;
        const float* Bg = WT + (size_t)colBase * GK + kt * BK;
#pragma unroll
        for (int i = 0; i < 4; i++) {               // A: 1024 x 16B
            int c = i * 256 + t;
            int row = c >> 3, c8 = c & 7;
            cp16(stg + SWZ(row * 128 + c8 * 16), Ag + (size_t)row * GK + c8 * 4);
        }
#pragma unroll
        for (int i = 0; i < 8; i++) {               // B: 2048 x 16B
            int c = i * 256 + t;
            int n = c >> 3, c8 = c & 7;
            cp16(stg + A_STAGE_B + SWZ(n * 128 + c8 * 16), Bg + (size_t)n * GK + c8 * 4);
        }
        CP_COMMIT();
    };

    // ---- per-lane ldmatrix address prep ----
    // A x4(mi,ks): row = wm + mi*16 + ((lane>>3)&1)*8 + (lane&7);
    //              colF = ks*8 + (lane>>4)*4
    const int rA0 = wm + ((lane >> 3) & 1) * 8 + (lane & 7);
    const uint32_t xorA  = (uint32_t)(rA0 & 7) * 16;     // (row&7) invariant under +16
    const uint32_t cAb   = (uint32_t)(lane >> 4) * 16;   // colF*4 base
    // B x4(ni pair, ks): n = wn + nj*16 + (lane>>4)*8 + (lane&7);
    //                    colF = ks*8 + ((lane>>3)&1)*4
    const int nB0 = wn + (lane >> 4) * 8 + (lane & 7);
    const uint32_t xorB  = (uint32_t)(nB0 & 7) * 16;
    const uint32_t cBb   = (uint32_t)((lane >> 3) & 1) * 16;

    float acc[2][16][4] = {};

    // preload tiles 0..2 into slots 0..2 (slot 3 filled at kt=0)
#pragma unroll
    for (int s = 0; s < 3; s++) load_stage(s, s);

    for (int kt = 0; kt < NKT; kt++) {
        const int rem = NKT - 1 - kt;
        if (rem >= 2)      asm volatile("cp.async.wait_group 2;" ::: "memory");
        else if (rem == 1) asm volatile("cp.async.wait_group 1;" ::: "memory");
        else               asm volatile("cp.async.wait_group 0;" ::: "memory");
        __syncthreads();

        // prefetch tile kt+3 into slot (kt+3)&3 == (kt-1)&3 (freed at barrier)
        if (kt + 3 < NKT) load_stage(kt + 3, (kt + 3) & 3);

        const int s = kt & 3;
        const uint32_t aBase0 = sb + s * STAGE_B + (uint32_t)rA0 * 128;
        const uint32_t bBase  = sb + s * STAGE_B + A_STAGE_B + (uint32_t)nB0 * 128;

#pragma unroll
        for (int ks = 0; ks < 4; ks++) {
            const uint32_t cA = (uint32_t)ks * 32 + cAb;   // colF*4 bytes
            const uint32_t cB = (uint32_t)ks * 32 + cBb;
            uint32_t afr[2][4];
            ldsm4(afr[0], aBase0 + (cA ^ xorA));
            ldsm4(afr[1], aBase0 + 16 * 128 + (cA ^ xorA));
            uint32_t bfr[16][2];
#pragma unroll
            for (int nj = 0; nj < 8; nj++) {               // covers ni=2nj, 2nj+1
                uint32_t d[4];
                ldsm4(d, bBase + (uint32_t)nj * 2048 + (cB ^ xorB));
                bfr[2 * nj][0] = d[0]; bfr[2 * nj][1] = d[1];
                bfr[2 * nj + 1][0] = d[2]; bfr[2 * nj + 1][1] = d[3];
            }
#pragma unroll
            for (int mi = 0; mi < 2; mi++)
#pragma unroll
                for (int ni = 0; ni < 16; ni++)
                    mma_tf32(acc[mi][ni], afr[mi], bfr[ni][0], bfr[ni][1]);
        }
    }

    // ---- epilogue ----
    const int g = lane >> 2, l4 = lane & 3;
#pragma unroll
    for (int mi = 0; mi < 2; mi++) {
        const size_t r0 = (size_t)rowBase + wm + mi * 16 + g;
#pragma unroll
        for (int ni = 0; ni < 16; ni++) {
            const int c = wn + ni * 8 + 2 * l4;
            const float b0v = bias_s[c], b1v = bias_s[c + 1];
            float v0 = acc[mi][ni][0] + b0v;
            float v1 = acc[mi][ni][1] + b1v;
            float v2 = acc[mi][ni][2] + b0v;
            float v3 = acc[mi][ni][3] + b1v;
            if (act) { v0 = fm_act(v0); v1 = fm_act(v1); v2 = fm_act(v2); v3 = fm_act(v3); }
            *reinterpret_cast<float2*>(&O[r0 * GN + colBase + c])       = make_float2(v0, v1);
            *reinterpret_cast<float2*>(&O[(r0 + 8) * GN + colBase + c]) = make_float2(v2, v3);
        }
    }
}

// ---------------------------------------------------------------------------
// kv partial + reduce (deterministic two-pass)
// ---------------------------------------------------------------------------
__global__ void kv_partial_kernel()
{
    __shared__ float ks_[32 * 64];
    __shared__ float vs_[32 * 64];
    const int chunk = blockIdx.x, h = blockIdx.y, b = blockIdx.z;
    const int t  = threadIdx.x;
    const int td = (t >> 4) * 4;
    const int te = (t & 15) * 4;

    float acc[4][4] = {};
    float ksacc[4]  = {};

    const size_t base = ((size_t)b * 8192) * 1024 + (size_t)h * 64;
    const float* Kb = g_K + base;
    const float* Vb = g_V + base;

    const int nStart = chunk * 512;
    for (int n0 = nStart; n0 < nStart + 512; n0 += 32) {
        __syncthreads();
#pragma unroll
        for (int i = 0; i < 2; i++) {
            int f  = i * 256 + t;
            int nn = f >> 4, c4 = (f & 15) * 4;
            *reinterpret_cast<float4*>(&ks_[nn * 64 + c4]) =
                *reinterpret_cast<const float4*>(&Kb[(size_t)(n0 + nn) * 1024 + c4]);
            *reinterpret_cast<float4*>(&vs_[nn * 64 + c4]) =
                *reinterpret_cast<const float4*>(&Vb[(size_t)(n0 + nn) * 1024 + c4]);
        }
        __syncthreads();
#pragma unroll 4
        for (int nn = 0; nn < 32; nn++) {
            float4 kk = *reinterpret_cast<const float4*>(&ks_[nn * 64 + td]);
            float4 vv = *reinterpret_cast<const float4*>(&vs_[nn * 64 + te]);
            float kq[4] = {kk.x, kk.y, kk.z, kk.w};
            float vq[4] = {vv.x, vv.y, vv.z, vv.w};
#pragma unroll
            for (int i = 0; i < 4; i++)
#pragma unroll
                for (int j = 0; j < 4; j++)
                    acc[i][j] += kq[i] * vq[j];
            if (te == 0) {
                ksacc[0] += kk.x; ksacc[1] += kk.y; ksacc[2] += kk.z; ksacc[3] += kk.w;
            }
        }
    }

    float* P = g_kvpart + (size_t)(((b * 16 + h) * 16) + chunk) * 4160;
#pragma unroll
    for (int i = 0; i < 4; i++)
#pragma unroll
        for (int j = 0; j < 4; j++)
            P[(td + i) * 64 + te + j] = acc[i][j];
    if (te == 0) {
#pragma unroll
        for (int i = 0; i < 4; i++) P[4096 + td + i] = ksacc[i];
    }
}

__global__ void kv_reduce_kernel()
{
    const int bh = blockIdx.x;
    const float* P = g_kvpart + (size_t)bh * 16 * 4160;
    for (int i = threadIdx.x; i < 4160; i += 256) {
        float s = 0.0f;
#pragma unroll
        for (int c = 0; c < 16; c++) s += P[c * 4160 + i];
        if (i < 4096) g_kv[bh * 4096 + i] = s;
        else          g_ksum[bh * 64 + (i - 4096)] = s;
    }
}

// ---------------------------------------------------------------------------
// scores: 2-row register blocking; output rna-rounded (feeds tf32 GEMM2).
// grid (128 chunks of 256 rows, 16 h), 128 threads.
// ---------------------------------------------------------------------------
__global__ void __launch_bounds__(128)
scores_kernel()
{
    extern __shared__ float sm[];
    float* kv_s   = sm;               // 4096
    float* ksum_s = sm + 4096;        // 64
    float* q_s    = sm + 4160;        // 256 * 65

    const int h  = blockIdx.y;
    const int r0 = blockIdx.x * 256;
    const int b  = r0 >> 13;
    const int bh = b * 16 + h;
    const int t  = threadIdx.x;

    for (int i = t; i < 4096; i += 128) kv_s[i] = g_kv[bh * 4096 + i];
    if (t < 64) ksum_s[t] = g_ksum[bh * 64 + t];

#pragma unroll
    for (int i = 0; i < 32; i++) {
        int f = i * 128 + t;
        int row = f >> 4, c4 = (f & 15) << 2;
        float4 qv = *reinterpret_cast<const float4*>(
            &g_Q[(size_t)(r0 + row) * 1024 + h * 64 + c4]);
        float* dst = &q_s[row * 65 + c4];
        dst[0] = qv.x; dst[1] = qv.y; dst[2] = qv.z; dst[3] = qv.w;
    }
    __syncthreads();

    float accA[64], accB[64];
#pragma unroll
    for (int e = 0; e < 64; e++) { accA[e] = 0.0f; accB[e] = 0.0f; }
    float zA = 0.0f, zB = 0.0f;
    const float* qa = &q_s[t * 65];
    const float* qb = &q_s[(t + 128) * 65];

    for (int d = 0; d < 64; d++) {
        float q0 = qa[d], q1 = qb[d];
        float ks = ksum_s[d];
        zA += q0 * ks;  zB += q1 * ks;
        const float4* kr = reinterpret_cast<const float4*>(&kv_s[d * 64]);
#pragma unroll
        for (int e4 = 0; e4 < 16; e4++) {
            float4 kv4 = kr[e4];
            accA[e4 * 4 + 0] += q0 * kv4.x;  accB[e4 * 4 + 0] += q1 * kv4.x;
            accA[e4 * 4 + 1] += q0 * kv4.y;  accB[e4 * 4 + 1] += q1 * kv4.y;
            accA[e4 * 4 + 2] += q0 * kv4.z;  accB[e4 * 4 + 2] += q1 * kv4.z;
            accA[e4 * 4 + 3] += q0 * kv4.w;  accB[e4 * 4 + 3] += q1 * kv4.w;
        }
    }

    __syncthreads();
    float zvA = 1.0f / (zA + 1e-6f);
    float zvB = 1.0f / (zB + 1e-6f);
#pragma unroll
    for (int e = 0; e < 64; e++) {
        q_s[t * 65 + e]         = rna_tf32(accA[e] * zvA);
        q_s[(t + 128) * 65 + e] = rna_tf32(accB[e] * zvB);
    }
    __syncthreads();

#pragma unroll
    for (int i = 0; i < 32; i++) {
        int f = i * 128 + t;
        int row = f >> 4, c4 = (f & 15) << 2;
        const float* src = &q_s[row * 65 + c4];
        float4 o = make_float4(src[0], src[1], src[2], src[3]);
        *reinterpret_cast<float4*>(&g_S[(size_t)(r0 + row) * 1024 + h * 64 + c4]) = o;
    }
}

// ---------------------------------------------------------------------------
// launch
// ---------------------------------------------------------------------------
extern "C" void kernel_launch(void* const* d_in, const int* in_sizes, int n_in,
                              void* d_out, int out_size)
{
    const float* x  = (const float*)d_in[0];
    const float* wq = (const float*)d_in[1];
    const float* bq = (const float*)d_in[2];
    const float* wk = (const float*)d_in[3];
    const float* bk = (const float*)d_in[4];
    const float* wv = (const float*)d_in[5];
    const float* bv = (const float*)d_in[6];
    const float* wo = (const float*)d_in[7];
    const float* bo = (const float*)d_in[8];
    float* out = (float*)d_out;
    (void)in_sizes; (void)n_in; (void)out_size;

    cudaFuncSetAttribute(tc_gemm<0>, cudaFuncAttributeMaxDynamicSharedMemorySize, GEMM_SMEM);
    cudaFuncSetAttribute(tc_gemm<1>, cudaFuncAttributeMaxDynamicSharedMemorySize, GEMM_SMEM);
    cudaFuncSetAttribute(scores_kernel, cudaFuncAttributeMaxDynamicSharedMemorySize, SCORES_SMEM);

    // 0) rna-round operands (removes all in-loop cvt; HMMA truncation exact)
    round_x_kernel<<<65536, 128>>>(x);
    transpose_w_kernel<<<dim3(32, 32, 4), dim3(32, 8)>>>(wq, wk, wv, wo);

    // 1) QKV projections
    tc_gemm<0><<<dim3(GN / BN, GM / BM, 3), 256, GEMM_SMEM>>>(bq, bk, bv, nullptr);

    // 2) kv outer-product + ksum
    kv_partial_kernel<<<dim3(16, 16, 4), 256>>>();
    kv_reduce_kernel<<<64, 256>>>();

    // 3) scores = (q @ kv) * z  (rna-rounded output)
    scores_kernel<<<dim3(128, 16), 128, SCORES_SMEM>>>();

    // 4) out = scores @ wo + bo
    tc_gemm<1><<<dim3(GN / BN, GM / BM, 1), 256, GEMM_SMEM>>>(bo, nullptr, nullptr, out);
}

// round 8
// speedup vs baseline: 1.2290x; 1.0689x over previous
#include <cuda_runtime.h>
#include <cstdint>

// ---------------------------------------------------------------------------
// LinearAttention B=4 N=8192 D=1024 H=16 Dh=64
// sm_100 base-ISA: mma.sync tf32 + ldmatrix + cp.async. 2 CTAs/SM GEMM.
// ---------------------------------------------------------------------------

constexpr int GM = 32768, GN = 1024, GK = 1024;
constexpr int BM = 128, BN = 128, BK = 32;
constexpr int NKT = GK / BK;                     // 32
constexpr int A_STAGE_B = BM * 128;              // 16384 B
constexpr int B_STAGE_B = BN * 128;              // 16384 B
constexpr int STAGE_B   = A_STAGE_B + B_STAGE_B; // 32768 B
constexpr int STAGES = 3;                        // ring, prefetch dist 2
constexpr int OFF_BIAS  = STAGES * STAGE_B;      // 98304
constexpr int GEMM_SMEM = OFF_BIAS + BN * 4;     // 98816 -> 2 CTAs/SM
constexpr int SCORES_SMEM = (4096 + 64 + 256 * 65) * 4;  // 83200

// scratch (device globals; no allocation allowed)
__device__ float g_X[(size_t)GM * GN];
__device__ float g_Q[(size_t)GM * GN];
__device__ float g_K[(size_t)GM * GN];
__device__ float g_V[(size_t)GM * GN];
__device__ float g_S[(size_t)GM * GN];
__device__ float g_WT[4][(size_t)GK * GN];       // W^T (n-major), tf32-rounded
__device__ float g_kvpart[1024 * 4160];
__device__ float g_kv[64 * 4096];
__device__ float g_ksum[64 * 64];

// ---------------------------------------------------------------------------
// helpers
// ---------------------------------------------------------------------------
__device__ __forceinline__ uint32_t smem_u32(const void* p) {
    uint32_t a;
    asm("{ .reg .u64 t; cvta.to.shared.u64 t, %1; cvt.u32.u64 %0, t; }" : "=r"(a) : "l"(p));
    return a;
}
__device__ __forceinline__ uint32_t f2tf(float x) {
    uint32_t r;
    asm("cvt.rna.tf32.f32 %0, %1;" : "=r"(r) : "f"(x));
    return r;
}
__device__ __forceinline__ float rna_tf32(float x) { return __uint_as_float(f2tf(x)); }

__device__ __forceinline__ void cp16(uint32_t s, const void* g) {
    asm volatile("cp.async.cg.shared.global [%0], [%1], 16;" :: "r"(s), "l"(g) : "memory");
}
#define CP_COMMIT() asm volatile("cp.async.commit_group;" ::: "memory")

__device__ __forceinline__ float fm_act(float x) { return x > 0.0f ? x + 1.0f : __expf(x); }

__device__ __forceinline__ void ldsm4(uint32_t* d, uint32_t addr) {
    asm volatile("ldmatrix.sync.aligned.m8n8.x4.shared.b16 {%0,%1,%2,%3}, [%4];"
                 : "=r"(d[0]), "=r"(d[1]), "=r"(d[2]), "=r"(d[3]) : "r"(addr));
}
__device__ __forceinline__ void mma_tf32(float* c, const uint32_t* a, uint32_t b0, uint32_t b1) {
    asm volatile(
        "mma.sync.aligned.m16n8k8.row.col.f32.tf32.tf32.f32 "
        "{%0,%1,%2,%3}, {%4,%5,%6,%7}, {%8,%9}, {%0,%1,%2,%3};"
        : "+f"(c[0]), "+f"(c[1]), "+f"(c[2]), "+f"(c[3])
        : "r"(a[0]), "r"(a[1]), "r"(a[2]), "r"(a[3]), "r"(b0), "r"(b1));
}

#define SWZ(off) ((off) ^ (((off) >> 3) & 0x70))

// ---------------------------------------------------------------------------
// pre-passes
// ---------------------------------------------------------------------------
__global__ void round_x_kernel(const float* __restrict__ x) {
    size_t i = ((size_t)blockIdx.x * 128 + threadIdx.x) * 4;
    float4 v = *reinterpret_cast<const float4*>(x + i);
    v.x = rna_tf32(v.x); v.y = rna_tf32(v.y); v.z = rna_tf32(v.z); v.w = rna_tf32(v.w);
    *reinterpret_cast<float4*>(g_X + i) = v;
}

__global__ void transpose_w_kernel(const float* __restrict__ w0, const float* __restrict__ w1,
                                   const float* __restrict__ w2, const float* __restrict__ w3) {
    __shared__ float tile[32][33];
    const float* W = (blockIdx.z == 0) ? w0 : (blockIdx.z == 1) ? w1 : (blockIdx.z == 2) ? w2 : w3;
    float* WT = &g_WT[blockIdx.z][0];
    int bx = blockIdx.x * 32, by = blockIdx.y * 32;   // bx: n, by: k
    int tx = threadIdx.x, ty = threadIdx.y;
#pragma unroll
    for (int i = 0; i < 32; i += 8)
        tile[ty + i][tx] = W[(size_t)(by + ty + i) * GN + bx + tx];
    __syncthreads();
#pragma unroll
    for (int i = 0; i < 32; i += 8)
        WT[(size_t)(bx + ty + i) * GK + by + tx] = rna_tf32(tile[tx][ty + i]);
}

// ---------------------------------------------------------------------------
// TF32 mma.sync GEMM, 3-stage ring, 2 CTAs/SM, ldmatrix fragments.
// 256 threads, warps 4(m) x 2(n); warp tile 32x64.
// Schedule: at iter kt -> wait_group(1|0), barrier, prefetch kt+2 into slot
// (kt+2)%3 == (kt-1)%3 (drained before this barrier), compute slot kt%3.
// ---------------------------------------------------------------------------
template <int MODE>
__global__ void __launch_bounds__(256, 2)
tc_gemm(const float* __restrict__ bias0, const float* __restrict__ bias1,
        const float* __restrict__ bias2, float* __restrict__ Oout)
{
    extern __shared__ __align__(128) char smem[];
    const uint32_t sb = smem_u32(smem);
    const int t = threadIdx.x, lane = t & 31, wid = t >> 5;
    const int z = blockIdx.z;

    const float* A;  const float* WT;  const float* bias;  float* O;  bool act;
    if (MODE == 0) {
        A = g_X; WT = &g_WT[z][0];
        bias = (z == 0) ? bias0 : (z == 1) ? bias1 : bias2;
        O = (z == 0) ? g_Q : (z == 1) ? g_K : g_V;
        act = (z < 2);
    } else {
        A = g_S; WT = &g_WT[3][0]; bias = bias0; O = Oout; act = false;
    }

    const int rowBase = blockIdx.y * BM;
    const int colBase = blockIdx.x * BN;
    const int wm = (wid & 3) * 32;      // 4 warps over 128 m
    const int wn = (wid >> 2) * 64;     // 2 warps over 128 n

    float* bias_s = reinterpret_cast<float*>(smem + OFF_BIAS);
    if (t < BN) bias_s[t] = bias[colBase + t];

    // ---- cp.async stage loader (SW128-swizzled 128B rows) ----
    auto load_stage = [&](int kt, int s) {
        const uint32_t stg = sb + s * STAGE_B;
        const float* Ag = A + (size_t)rowBase * GK + kt * BK;
        const float* Bg = WT + (size_t)colBase * GK + kt * BK;
#pragma unroll
        for (int i = 0; i < 4; i++) {               // A: 1024 x 16B
            int c = i * 256 + t;
            int row = c >> 3, c8 = c & 7;
            cp16(stg + SWZ(row * 128 + c8 * 16), Ag + (size_t)row * GK + c8 * 4);
        }
#pragma unroll
        for (int i = 0; i < 4; i++) {               // B: 1024 x 16B
            int c = i * 256 + t;
            int n = c >> 3, c8 = c & 7;
            cp16(stg + A_STAGE_B + SWZ(n * 128 + c8 * 16), Bg + (size_t)n * GK + c8 * 4);
        }
        CP_COMMIT();
    };

    // ---- per-lane ldmatrix address prep (validated in round 7) ----
    const int rA0 = wm + ((lane >> 3) & 1) * 8 + (lane & 7);
    const uint32_t xorA = (uint32_t)(rA0 & 7) * 16;
    const uint32_t cAb  = (uint32_t)(lane >> 4) * 16;
    const int nB0 = wn + (lane >> 4) * 8 + (lane & 7);
    const uint32_t xorB = (uint32_t)(nB0 & 7) * 16;
    const uint32_t cBb  = (uint32_t)((lane >> 3) & 1) * 16;

    float acc[2][8][4] = {};

    load_stage(0, 0);
    load_stage(1, 1);

    for (int kt = 0; kt < NKT; kt++) {
        if (kt < NKT - 1) asm volatile("cp.async.wait_group 1;" ::: "memory");
        else              asm volatile("cp.async.wait_group 0;" ::: "memory");
        __syncthreads();

        if (kt + 2 < NKT) load_stage(kt + 2, (kt + 2) % 3);

        const int s = kt % 3;
        const uint32_t aBase0 = sb + s * STAGE_B + (uint32_t)rA0 * 128;
        const uint32_t bBase  = sb + s * STAGE_B + A_STAGE_B + (uint32_t)nB0 * 128;

#pragma unroll
        for (int ks = 0; ks < 4; ks++) {
            const uint32_t cA = (uint32_t)ks * 32 + cAb;
            const uint32_t cB = (uint32_t)ks * 32 + cBb;
            uint32_t afr[2][4];
            ldsm4(afr[0], aBase0 + (cA ^ xorA));
            ldsm4(afr[1], aBase0 + 16 * 128 + (cA ^ xorA));
            uint32_t bfr[8][2];
#pragma unroll
            for (int nj = 0; nj < 4; nj++) {         // covers ni = 2nj, 2nj+1
                uint32_t d[4];
                ldsm4(d, bBase + (uint32_t)nj * 2048 + (cB ^ xorB));
                bfr[2 * nj][0] = d[0]; bfr[2 * nj][1] = d[1];
                bfr[2 * nj + 1][0] = d[2]; bfr[2 * nj + 1][1] = d[3];
            }
#pragma unroll
            for (int mi = 0; mi < 2; mi++)
#pragma unroll
                for (int ni = 0; ni < 8; ni++)
                    mma_tf32(acc[mi][ni], afr[mi], bfr[ni][0], bfr[ni][1]);
        }
    }

    // ---- epilogue ----
    const int g = lane >> 2, l4 = lane & 3;
#pragma unroll
    for (int mi = 0; mi < 2; mi++) {
        const size_t r0 = (size_t)rowBase + wm + mi * 16 + g;
#pragma unroll
        for (int ni = 0; ni < 8; ni++) {
            const int c = wn + ni * 8 + 2 * l4;
            const float b0v = bias_s[c], b1v = bias_s[c + 1];
            float v0 = acc[mi][ni][0] + b0v;
            float v1 = acc[mi][ni][1] + b1v;
            float v2 = acc[mi][ni][2] + b0v;
            float v3 = acc[mi][ni][3] + b1v;
            if (act) { v0 = fm_act(v0); v1 = fm_act(v1); v2 = fm_act(v2); v3 = fm_act(v3); }
            *reinterpret_cast<float2*>(&O[r0 * GN + colBase + c])       = make_float2(v0, v1);
            *reinterpret_cast<float2*>(&O[(r0 + 8) * GN + colBase + c]) = make_float2(v2, v3);
        }
    }
}

// ---------------------------------------------------------------------------
// kv partial + reduce (deterministic two-pass)
// ---------------------------------------------------------------------------
__global__ void kv_partial_kernel()
{
    __shared__ float ks_[32 * 64];
    __shared__ float vs_[32 * 64];
    const int chunk = blockIdx.x, h = blockIdx.y, b = blockIdx.z;
    const int t  = threadIdx.x;
    const int td = (t >> 4) * 4;
    const int te = (t & 15) * 4;

    float acc[4][4] = {};
    float ksacc[4]  = {};

    const size_t base = ((size_t)b * 8192) * 1024 + (size_t)h * 64;
    const float* Kb = g_K + base;
    const float* Vb = g_V + base;

    const int nStart = chunk * 512;
    for (int n0 = nStart; n0 < nStart + 512; n0 += 32) {
        __syncthreads();
#pragma unroll
        for (int i = 0; i < 2; i++) {
            int f  = i * 256 + t;
            int nn = f >> 4, c4 = (f & 15) * 4;
            *reinterpret_cast<float4*>(&ks_[nn * 64 + c4]) =
                *reinterpret_cast<const float4*>(&Kb[(size_t)(n0 + nn) * 1024 + c4]);
            *reinterpret_cast<float4*>(&vs_[nn * 64 + c4]) =
                *reinterpret_cast<const float4*>(&Vb[(size_t)(n0 + nn) * 1024 + c4]);
        }
        __syncthreads();
#pragma unroll 4
        for (int nn = 0; nn < 32; nn++) {
            float4 kk = *reinterpret_cast<const float4*>(&ks_[nn * 64 + td]);
            float4 vv = *reinterpret_cast<const float4*>(&vs_[nn * 64 + te]);
            float kq[4] = {kk.x, kk.y, kk.z, kk.w};
            float vq[4] = {vv.x, vv.y, vv.z, vv.w};
#pragma unroll
            for (int i = 0; i < 4; i++)
#pragma unroll
                for (int j = 0; j < 4; j++)
                    acc[i][j] += kq[i] * vq[j];
            if (te == 0) {
                ksacc[0] += kk.x; ksacc[1] += kk.y; ksacc[2] += kk.z; ksacc[3] += kk.w;
            }
        }
    }

    float* P = g_kvpart + (size_t)(((b * 16 + h) * 16) + chunk) * 4160;
#pragma unroll
    for (int i = 0; i < 4; i++)
#pragma unroll
        for (int j = 0; j < 4; j++)
            P[(td + i) * 64 + te + j] = acc[i][j];
    if (te == 0) {
#pragma unroll
        for (int i = 0; i < 4; i++) P[4096 + td + i] = ksacc[i];
    }
}

__global__ void kv_reduce_kernel()
{
    const int bh = blockIdx.x;
    const float* P = g_kvpart + (size_t)bh * 16 * 4160;
    for (int i = threadIdx.x; i < 4160; i += 256) {
        float s = 0.0f;
#pragma unroll
        for (int c = 0; c < 16; c++) s += P[c * 4160 + i];
        if (i < 4096) g_kv[bh * 4096 + i] = s;
        else          g_ksum[bh * 64 + (i - 4096)] = s;
    }
}

// ---------------------------------------------------------------------------
// scores: 2-row register blocking; output rna-rounded (feeds tf32 GEMM2).
// ---------------------------------------------------------------------------
__global__ void __launch_bounds__(128)
scores_kernel()
{
    extern __shared__ float sm[];
    float* kv_s   = sm;               // 4096
    float* ksum_s = sm + 4096;        // 64
    float* q_s    = sm + 4160;        // 256 * 65

    const int h  = blockIdx.y;
    const int r0 = blockIdx.x * 256;
    const int b  = r0 >> 13;
    const int bh = b * 16 + h;
    const int t  = threadIdx.x;

    for (int i = t; i < 4096; i += 128) kv_s[i] = g_kv[bh * 4096 + i];
    if (t < 64) ksum_s[t] = g_ksum[bh * 64 + t];

#pragma unroll
    for (int i = 0; i < 32; i++) {
        int f = i * 128 + t;
        int row = f >> 4, c4 = (f & 15) << 2;
        float4 qv = *reinterpret_cast<const float4*>(
            &g_Q[(size_t)(r0 + row) * 1024 + h * 64 + c4]);
        float* dst = &q_s[row * 65 + c4];
        dst[0] = qv.x; dst[1] = qv.y; dst[2] = qv.z; dst[3] = qv.w;
    }
    __syncthreads();

    float accA[64], accB[64];
#pragma unroll
    for (int e = 0; e < 64; e++) { accA[e] = 0.0f; accB[e] = 0.0f; }
    float zA = 0.0f, zB = 0.0f;
    const float* qa = &q_s[t * 65];
    const float* qb = &q_s[(t + 128) * 65];

    for (int d = 0; d < 64; d++) {
        float q0 = qa[d], q1 = qb[d];
        float ks = ksum_s[d];
        zA += q0 * ks;  zB += q1 * ks;
        const float4* kr = reinterpret_cast<const float4*>(&kv_s[d * 64]);
#pragma unroll
        for (int e4 = 0; e4 < 16; e4++) {
            float4 kv4 = kr[e4];
            accA[e4 * 4 + 0] += q0 * kv4.x;  accB[e4 * 4 + 0] += q1 * kv4.x;
            accA[e4 * 4 + 1] += q0 * kv4.y;  accB[e4 * 4 + 1] += q1 * kv4.y;
            accA[e4 * 4 + 2] += q0 * kv4.z;  accB[e4 * 4 + 2] += q1 * kv4.z;
            accA[e4 * 4 + 3] += q0 * kv4.w;  accB[e4 * 4 + 3] += q1 * kv4.w;
        }
    }

    __syncthreads();
    float zvA = 1.0f / (zA + 1e-6f);
    float zvB = 1.0f / (zB + 1e-6f);
#pragma unroll
    for (int e = 0; e < 64; e++) {
        q_s[t * 65 + e]         = rna_tf32(accA[e] * zvA);
        q_s[(t + 128) * 65 + e] = rna_tf32(accB[e] * zvB);
    }
    __syncthreads();

#pragma unroll
    for (int i = 0; i < 32; i++) {
        int f = i * 128 + t;
        int row = f >> 4, c4 = (f & 15) << 2;
        const float* src = &q_s[row * 65 + c4];
        float4 o = make_float4(src[0], src[1], src[2], src[3]);
        *reinterpret_cast<float4*>(&g_S[(size_t)(r0 + row) * 1024 + h * 64 + c4]) = o;
    }
}

// ---------------------------------------------------------------------------
// launch
// ---------------------------------------------------------------------------
extern "C" void kernel_launch(void* const* d_in, const int* in_sizes, int n_in,
                              void* d_out, int out_size)
{
    const float* x  = (const float*)d_in[0];
    const float* wq = (const float*)d_in[1];
    const float* bq = (const float*)d_in[2];
    const float* wk = (const float*)d_in[3];
    const float* bk = (const float*)d_in[4];
    const float* wv = (const float*)d_in[5];
    const float* bv = (const float*)d_in[6];
    const float* wo = (const float*)d_in[7];
    const float* bo = (const float*)d_in[8];
    float* out = (float*)d_out;
    (void)in_sizes; (void)n_in; (void)out_size;

    cudaFuncSetAttribute(tc_gemm<0>, cudaFuncAttributeMaxDynamicSharedMemorySize, GEMM_SMEM);
    cudaFuncSetAttribute(tc_gemm<1>, cudaFuncAttributeMaxDynamicSharedMemorySize, GEMM_SMEM);
    cudaFuncSetAttribute(scores_kernel, cudaFuncAttributeMaxDynamicSharedMemorySize, SCORES_SMEM);

    // 0) rna-round operands (HMMA truncation then exact)
    round_x_kernel<<<65536, 128>>>(x);
    transpose_w_kernel<<<dim3(32, 32, 4), dim3(32, 8)>>>(wq, wk, wv, wo);

    // 1) QKV projections
    tc_gemm<0><<<dim3(GN / BN, GM / BM, 3), 256, GEMM_SMEM>>>(bq, bk, bv, nullptr);

    // 2) kv outer-product + ksum
    kv_partial_kernel<<<dim3(16, 16, 4), 256>>>();
    kv_reduce_kernel<<<64, 256>>>();

    // 3) scores = (q @ kv) * z  (rna-rounded output)
    scores_kernel<<<dim3(128, 16), 128, SCORES_SMEM>>>();

    // 4) out = scores @ wo + bo
    tc_gemm<1><<<dim3(GN / BN, GM / BM, 1), 256, GEMM_SMEM>>>(bo, nullptr, nullptr, out);
}

// round 9
// speedup vs baseline: 1.2293x; 1.0002x over previous
#include <cuda_runtime.h>
#include <cstdint>

// ---------------------------------------------------------------------------
// LinearAttention B=4 N=8192 D=1024 H=16 Dh=64
// sm_100 base-ISA: mma.sync tf32 + ldmatrix + cp.async. 2 CTAs/SM GEMM.
// ---------------------------------------------------------------------------

constexpr int GM = 32768, GN = 1024, GK = 1024;
constexpr int BM = 128, BN = 128, BK = 32;
constexpr int NKT = GK / BK;                     // 32
constexpr int A_STAGE_B = BM * 128;              // 16384 B
constexpr int B_STAGE_B = BN * 128;              // 16384 B
constexpr int STAGE_B   = A_STAGE_B + B_STAGE_B; // 32768 B
constexpr int STAGES = 3;                        // ring, prefetch dist 2
constexpr int OFF_BIAS  = STAGES * STAGE_B;      // 98304
constexpr int GEMM_SMEM = OFF_BIAS + BN * 4;     // 98816 -> 2 CTAs/SM
constexpr int SCORES_SMEM = (4096 + 64 + 256 * 65) * 4;  // 83200

// scratch (device globals; no allocation allowed)
__device__ float g_X[(size_t)GM * GN];
__device__ float g_Q[(size_t)GM * GN];
__device__ float g_K[(size_t)GM * GN];
__device__ float g_V[(size_t)GM * GN];
__device__ float g_S[(size_t)GM * GN];
__device__ float g_WT[4][(size_t)GK * GN];       // W^T (n-major), tf32-rounded
__device__ float g_kvpart[1024 * 4160];
__device__ float g_kv[64 * 4096];
__device__ float g_ksum[64 * 64];

// ---------------------------------------------------------------------------
// helpers
// ---------------------------------------------------------------------------
__device__ __forceinline__ uint32_t smem_u32(const void* p) {
    uint32_t a;
    asm("{ .reg .u64 t; cvta.to.shared.u64 t, %1; cvt.u32.u64 %0, t; }" : "=r"(a) : "l"(p));
    return a;
}
__device__ __forceinline__ uint32_t f2tf(float x) {
    uint32_t r;
    asm("cvt.rna.tf32.f32 %0, %1;" : "=r"(r) : "f"(x));
    return r;
}
__device__ __forceinline__ float rna_tf32(float x) { return __uint_as_float(f2tf(x)); }

__device__ __forceinline__ void cp16(uint32_t s, const void* g) {
    asm volatile("cp.async.cg.shared.global [%0], [%1], 16;" :: "r"(s), "l"(g) : "memory");
}
#define CP_COMMIT() asm volatile("cp.async.commit_group;" ::: "memory")

__device__ __forceinline__ float fm_act(float x) { return x > 0.0f ? x + 1.0f : __expf(x); }

__device__ __forceinline__ void ldsm4(uint32_t* d, uint32_t addr) {
    asm volatile("ldmatrix.sync.aligned.m8n8.x4.shared.b16 {%0,%1,%2,%3}, [%4];"
                 : "=r"(d[0]), "=r"(d[1]), "=r"(d[2]), "=r"(d[3]) : "r"(addr));
}
__device__ __forceinline__ void mma_tf32(float* c, const uint32_t* a, uint32_t b0, uint32_t b1) {
    asm volatile(
        "mma.sync.aligned.m16n8k8.row.col.f32.tf32.tf32.f32 "
        "{%0,%1,%2,%3}, {%4,%5,%6,%7}, {%8,%9}, {%0,%1,%2,%3};"
        : "+f"(c[0]), "+f"(c[1]), "+f"(c[2]), "+f"(c[3])
        : "r"(a[0]), "r"(a[1]), "r"(a[2]), "r"(a[3]), "r"(b0), "r"(b1));
}

#define SWZ(off) ((off) ^ (((off) >> 3) & 0x70))

// ---------------------------------------------------------------------------
// pre-passes
// ---------------------------------------------------------------------------
__global__ void round_x_kernel(const float* __restrict__ x) {
    size_t i = ((size_t)blockIdx.x * 128 + threadIdx.x) * 4;
    float4 v = *reinterpret_cast<const float4*>(x + i);
    v.x = rna_tf32(v.x); v.y = rna_tf32(v.y); v.z = rna_tf32(v.z); v.w = rna_tf32(v.w);
    *reinterpret_cast<float4*>(g_X + i) = v;
}

__global__ void transpose_w_kernel(const float* __restrict__ w0, const float* __restrict__ w1,
                                   const float* __restrict__ w2, const float* __restrict__ w3) {
    __shared__ float tile[32][33];
    const float* W = (blockIdx.z == 0) ? w0 : (blockIdx.z == 1) ? w1 : (blockIdx.z == 2) ? w2 : w3;
    float* WT = &g_WT[blockIdx.z][0];
    int bx = blockIdx.x * 32, by = blockIdx.y * 32;   // bx: n, by: k
    int tx = threadIdx.x, ty = threadIdx.y;
#pragma unroll
    for (int i = 0; i < 32; i += 8)
        tile[ty + i][tx] = W[(size_t)(by + ty + i) * GN + bx + tx];
    __syncthreads();
#pragma unroll
    for (int i = 0; i < 32; i += 8)
        WT[(size_t)(bx + ty + i) * GK + by + tx] = rna_tf32(tile[tx][ty + i]);
}

// ---------------------------------------------------------------------------
// TF32 mma.sync GEMM, 3-stage ring, 2 CTAs/SM, ldmatrix fragments.
// 256 threads, warps 4(m) x 2(n); warp tile 32x64.
// Schedule: at iter kt -> wait_group(1|0), barrier, prefetch kt+2 into slot
// (kt+2)%3 == (kt-1)%3 (drained before this barrier), compute slot kt%3.
// ---------------------------------------------------------------------------
template <int MODE>
__global__ void __launch_bounds__(256, 2)
tc_gemm(const float* __restrict__ bias0, const float* __restrict__ bias1,
        const float* __restrict__ bias2, float* __restrict__ Oout)
{
    extern __shared__ __align__(128) char smem[];
    const uint32_t sb = smem_u32(smem);
    const int t = threadIdx.x, lane = t & 31, wid = t >> 5;
    const int z = blockIdx.z;

    const float* A;  const float* WT;  const float* bias;  float* O;  bool act;
    if (MODE == 0) {
        A = g_X; WT = &g_WT[z][0];
        bias = (z == 0) ? bias0 : (z == 1) ? bias1 : bias2;
        O = (z == 0) ? g_Q : (z == 1) ? g_K : g_V;
        act = (z < 2);
    } else {
        A = g_S; WT = &g_WT[3][0]; bias = bias0; O = Oout; act = false;
    }

    const int rowBase = blockIdx.y * BM;
    const int colBase = blockIdx.x * BN;
    const int wm = (wid & 3) * 32;      // 4 warps over 128 m
    const int wn = (wid >> 2) * 64;     // 2 warps over 128 n

    float* bias_s = reinterpret_cast<float*>(smem + OFF_BIAS);
    if (t < BN) bias_s[t] = bias[colBase + t];

    // ---- cp.async stage loader (SW128-swizzled 128B rows) ----
    auto load_stage = [&](int kt, int s) {
        const uint32_t stg = sb + s * STAGE_B;
        const float* Ag = A + (size_t)rowBase * GK + kt * BK;
        const float* Bg = WT + (size_t)colBase * GK + kt * BK;
#pragma unroll
        for (int i = 0; i < 4; i++) {               // A: 1024 x 16B
            int c = i * 256 + t;
            int row = c >> 3, c8 = c & 7;
            cp16(stg + SWZ(row * 128 + c8 * 16), Ag + (size_t)row * GK + c8 * 4);
        }
#pragma unroll
        for (int i = 0; i < 4; i++) {               // B: 1024 x 16B
            int c = i * 256 + t;
            int n = c >> 3, c8 = c & 7;
            cp16(stg + A_STAGE_B + SWZ(n * 128 + c8 * 16), Bg + (size_t)n * GK + c8 * 4);
        }
        CP_COMMIT();
    };

    // ---- per-lane ldmatrix address prep (validated in round 7) ----
    const int rA0 = wm + ((lane >> 3) & 1) * 8 + (lane & 7);
    const uint32_t xorA = (uint32_t)(rA0 & 7) * 16;
    const uint32_t cAb  = (uint32_t)(lane >> 4) * 16;
    const int nB0 = wn + (lane >> 4) * 8 + (lane & 7);
    const uint32_t xorB = (uint32_t)(nB0 & 7) * 16;
    const uint32_t cBb  = (uint32_t)((lane >> 3) & 1) * 16;

    float acc[2][8][4] = {};

    load_stage(0, 0);
    load_stage(1, 1);

    for (int kt = 0; kt < NKT; kt++) {
        if (kt < NKT - 1) asm volatile("cp.async.wait_group 1;" ::: "memory");
        else              asm volatile("cp.async.wait_group 0;" ::: "memory");
        __syncthreads();

        if (kt + 2 < NKT) load_stage(kt + 2, (kt + 2) % 3);

        const int s = kt % 3;
        const uint32_t aBase0 = sb + s * STAGE_B + (uint32_t)rA0 * 128;
        const uint32_t bBase  = sb + s * STAGE_B + A_STAGE_B + (uint32_t)nB0 * 128;

#pragma unroll
        for (int ks = 0; ks < 4; ks++) {
            const uint32_t cA = (uint32_t)ks * 32 + cAb;
            const uint32_t cB = (uint32_t)ks * 32 + cBb;
            uint32_t afr[2][4];
            ldsm4(afr[0], aBase0 + (cA ^ xorA));
            ldsm4(afr[1], aBase0 + 16 * 128 + (cA ^ xorA));
            uint32_t bfr[8][2];
#pragma unroll
            for (int nj = 0; nj < 4; nj++) {         // covers ni = 2nj, 2nj+1
                uint32_t d[4];
                ldsm4(d, bBase + (uint32_t)nj * 2048 + (cB ^ xorB));
                bfr[2 * nj][0] = d[0]; bfr[2 * nj][1] = d[1];
                bfr[2 * nj + 1][0] = d[2]; bfr[2 * nj + 1][1] = d[3];
            }
#pragma unroll
            for (int mi = 0; mi < 2; mi++)
#pragma unroll
                for (int ni = 0; ni < 8; ni++)
                    mma_tf32(acc[mi][ni], afr[mi], bfr[ni][0], bfr[ni][1]);
        }
    }

    // ---- epilogue ----
    const int g = lane >> 2, l4 = lane & 3;
#pragma unroll
    for (int mi = 0; mi < 2; mi++) {
        const size_t r0 = (size_t)rowBase + wm + mi * 16 + g;
#pragma unroll
        for (int ni = 0; ni < 8; ni++) {
            const int c = wn + ni * 8 + 2 * l4;
            const float b0v = bias_s[c], b1v = bias_s[c + 1];
            float v0 = acc[mi][ni][0] + b0v;
            float v1 = acc[mi][ni][1] + b1v;
            float v2 = acc[mi][ni][2] + b0v;
            float v3 = acc[mi][ni][3] + b1v;
            if (act) { v0 = fm_act(v0); v1 = fm_act(v1); v2 = fm_act(v2); v3 = fm_act(v3); }
            *reinterpret_cast<float2*>(&O[r0 * GN + colBase + c])       = make_float2(v0, v1);
            *reinterpret_cast<float2*>(&O[(r0 + 8) * GN + colBase + c]) = make_float2(v2, v3);
        }
    }
}

// ---------------------------------------------------------------------------
// kv partial + reduce (deterministic two-pass)
// ---------------------------------------------------------------------------
__global__ void kv_partial_kernel()
{
    __shared__ float ks_[32 * 64];
    __shared__ float vs_[32 * 64];
    const int chunk = blockIdx.x, h = blockIdx.y, b = blockIdx.z;
    const int t  = threadIdx.x;
    const int td = (t >> 4) * 4;
    const int te = (t & 15) * 4;

    float acc[4][4] = {};
    float ksacc[4]  = {};

    const size_t base = ((size_t)b * 8192) * 1024 + (size_t)h * 64;
    const float* Kb = g_K + base;
    const float* Vb = g_V + base;

    const int nStart = chunk * 512;
    for (int n0 = nStart; n0 < nStart + 512; n0 += 32) {
        __syncthreads();
#pragma unroll
        for (int i = 0; i < 2; i++) {
            int f  = i * 256 + t;
            int nn = f >> 4, c4 = (f & 15) * 4;
            *reinterpret_cast<float4*>(&ks_[nn * 64 + c4]) =
                *reinterpret_cast<const float4*>(&Kb[(size_t)(n0 + nn) * 1024 + c4]);
            *reinterpret_cast<float4*>(&vs_[nn * 64 + c4]) =
                *reinterpret_cast<const float4*>(&Vb[(size_t)(n0 + nn) * 1024 + c4]);
        }
        __syncthreads();
#pragma unroll 4
        for (int nn = 0; nn < 32; nn++) {
            float4 kk = *reinterpret_cast<const float4*>(&ks_[nn * 64 + td]);
            float4 vv = *reinterpret_cast<const float4*>(&vs_[nn * 64 + te]);
            float kq[4] = {kk.x, kk.y, kk.z, kk.w};
            float vq[4] = {vv.x, vv.y, vv.z, vv.w};
#pragma unroll
            for (int i = 0; i < 4; i++)
#pragma unroll
                for (int j = 0; j < 4; j++)
                    acc[i][j] += kq[i] * vq[j];
            if (te == 0) {
                ksacc[0] += kk.x; ksacc[1] += kk.y; ksacc[2] += kk.z; ksacc[3] += kk.w;
            }
        }
    }

    float* P = g_kvpart + (size_t)(((b * 16 + h) * 16) + chunk) * 4160;
#pragma unroll
    for (int i = 0; i < 4; i++)
#pragma unroll
        for (int j = 0; j < 4; j++)
            P[(td + i) * 64 + te + j] = acc[i][j];
    if (te == 0) {
#pragma unroll
        for (int i = 0; i < 4; i++) P[4096 + td + i] = ksacc[i];
    }
}

__global__ void kv_reduce_kernel()
{
    const int bh = blockIdx.x;
    const float* P = g_kvpart + (size_t)bh * 16 * 4160;
    for (int i = threadIdx.x; i < 4160; i += 256) {
        float s = 0.0f;
#pragma unroll
        for (int c = 0; c < 16; c++) s += P[c * 4160 + i];
        if (i < 4096) g_kv[bh * 4096 + i] = s;
        else          g_ksum[bh * 64 + (i - 4096)] = s;
    }
}

// ---------------------------------------------------------------------------
// scores: 2-row register blocking; output rna-rounded (feeds tf32 GEMM2).
// ---------------------------------------------------------------------------
__global__ void __launch_bounds__(128)
scores_kernel()
{
    extern __shared__ float sm[];
    float* kv_s   = sm;               // 4096
    float* ksum_s = sm + 4096;        // 64
    float* q_s    = sm + 4160;        // 256 * 65

    const int h  = blockIdx.y;
    const int r0 = blockIdx.x * 256;
    const int b  = r0 >> 13;
    const int bh = b * 16 + h;
    const int t  = threadIdx.x;

    for (int i = t; i < 4096; i += 128) kv_s[i] = g_kv[bh * 4096 + i];
    if (t < 64) ksum_s[t] = g_ksum[bh * 64 + t];

#pragma unroll
    for (int i = 0; i < 32; i++) {
        int f = i * 128 + t;
        int row = f >> 4, c4 = (f & 15) << 2;
        float4 qv = *reinterpret_cast<const float4*>(
            &g_Q[(size_t)(r0 + row) * 1024 + h * 64 + c4]);
        float* dst = &q_s[row * 65 + c4];
        dst[0] = qv.x; dst[1] = qv.y; dst[2] = qv.z; dst[3] = qv.w;
    }
    __syncthreads();

    float accA[64], accB[64];
#pragma unroll
    for (int e = 0; e < 64; e++) { accA[e] = 0.0f; accB[e] = 0.0f; }
    float zA = 0.0f, zB = 0.0f;
    const float* qa = &q_s[t * 65];
    const float* qb = &q_s[(t + 128) * 65];

    for (int d = 0; d < 64; d++) {
        float q0 = qa[d], q1 = qb[d];
        float ks = ksum_s[d];
        zA += q0 * ks;  zB += q1 * ks;
        const float4* kr = reinterpret_cast<const float4*>(&kv_s[d * 64]);
#pragma unroll
        for (int e4 = 0; e4 < 16; e4++) {
            float4 kv4 = kr[e4];
            accA[e4 * 4 + 0] += q0 * kv4.x;  accB[e4 * 4 + 0] += q1 * kv4.x;
            accA[e4 * 4 + 1] += q0 * kv4.y;  accB[e4 * 4 + 1] += q1 * kv4.y;
            accA[e4 * 4 + 2] += q0 * kv4.z;  accB[e4 * 4 + 2] += q1 * kv4.z;
            accA[e4 * 4 + 3] += q0 * kv4.w;  accB[e4 * 4 + 3] += q1 * kv4.w;
        }
    }

    __syncthreads();
    float zvA = 1.0f / (zA + 1e-6f);
    float zvB = 1.0f / (zB + 1e-6f);
#pragma unroll
    for (int e = 0; e < 64; e++) {
        q_s[t * 65 + e]         = rna_tf32(accA[e] * zvA);
        q_s[(t + 128) * 65 + e] = rna_tf32(accB[e] * zvB);
    }
    __syncthreads();

#pragma unroll
    for (int i = 0; i < 32; i++) {
        int f = i * 128 + t;
        int row = f >> 4, c4 = (f & 15) << 2;
        const float* src = &q_s[row * 65 + c4];
        float4 o = make_float4(src[0], src[1], src[2], src[3]);
        *reinterpret_cast<float4*>(&g_S[(size_t)(r0 + row) * 1024 + h * 64 + c4]) = o;
    }
}

// ---------------------------------------------------------------------------
// launch
// ---------------------------------------------------------------------------
extern "C" void kernel_launch(void* const* d_in, const int* in_sizes, int n_in,
                              void* d_out, int out_size)
{
    const float* x  = (const float*)d_in[0];
    const float* wq = (const float*)d_in[1];
    const float* bq = (const float*)d_in[2];
    const float* wk = (const float*)d_in[3];
    const float* bk = (const float*)d_in[4];
    const float* wv = (const float*)d_in[5];
    const float* bv = (const float*)d_in[6];
    const float* wo = (const float*)d_in[7];
    const float* bo = (const float*)d_in[8];
    float* out = (float*)d_out;
    (void)in_sizes; (void)n_in; (void)out_size;

    cudaFuncSetAttribute(tc_gemm<0>, cudaFuncAttributeMaxDynamicSharedMemorySize, GEMM_SMEM);
    cudaFuncSetAttribute(tc_gemm<1>, cudaFuncAttributeMaxDynamicSharedMemorySize, GEMM_SMEM);
    cudaFuncSetAttribute(scores_kernel, cudaFuncAttributeMaxDynamicSharedMemorySize, SCORES_SMEM);

    // 0) rna-round operands (HMMA truncation then exact)
    round_x_kernel<<<65536, 128>>>(x);
    transpose_w_kernel<<<dim3(32, 32, 4), dim3(32, 8)>>>(wq, wk, wv, wo);

    // 1) QKV projections
    tc_gemm<0><<<dim3(GN / BN, GM / BM, 3), 256, GEMM_SMEM>>>(bq, bk, bv, nullptr);

    // 2) kv outer-product + ksum
    kv_partial_kernel<<<dim3(16, 16, 4), 256>>>();
    kv_reduce_kernel<<<64, 256>>>();

    // 3) scores = (q @ kv) * z  (rna-rounded output)
    scores_kernel<<<dim3(128, 16), 128, SCORES_SMEM>>>();

    // 4) out = scores @ wo + bo
    tc_gemm<1><<<dim3(GN / BN, GM / BM, 1), 256, GEMM_SMEM>>>(bo, nullptr, nullptr, out);
}